// round 5
// baseline (speedup 1.0000x reference)
#include <cuda_runtime.h>

#define NN 100000
#define EE 800000
#define FULL 0xffffffffu

// ---------------- device scratch (no allocs allowed) ----------------
__device__ float g_key[NN * 128];
__device__ float g_query[NN * 128];
__device__ float g_value[NN * 128];
__device__ float g_aggr[NN * 128];
__device__ float g_G[NN * 64];     // [n][h][i] : per-node folded w_ek·query
__device__ float g_denom[NN * 4];
__device__ float g_wrbf[42 * 32];  // w_rbf0 @ w_rbf1
__device__ float g_wsbf[16 * 32];  // w_sbf0 @ w_sbf1

// ---------------- K0: fold weight pairs ----------------
__global__ void combine_weights_kernel(const float* __restrict__ w_rbf0,
                                       const float* __restrict__ w_rbf1,
                                       const float* __restrict__ w_sbf0,
                                       const float* __restrict__ w_sbf1)
{
    int t = blockIdx.x * blockDim.x + threadIdx.x;
    if (t < 42 * 32) {
        int i = t >> 5, o = t & 31;
        float s = 0.f;
        #pragma unroll
        for (int k = 0; k < 32; k++) s = fmaf(w_rbf0[i * 32 + k], w_rbf1[k * 32 + o], s);
        g_wrbf[t] = s;
    }
    if (t < 16 * 32) {
        int i = t >> 5, o = t & 31;
        float s = 0.f;
        #pragma unroll
        for (int k = 0; k < 32; k++) s = fmaf(w_sbf0[i * 32 + k], w_sbf1[k * 32 + o], s);
        g_wsbf[t] = s;
    }
}

// ---------------- K1: per-node key/query/value/skip + G ----------------
// one warp per node; j = 4*lane + q column mapping; weights staged in smem
__global__ __launch_bounds__(256)
void node_kernel(const float* __restrict__ x, const float* __restrict__ rbf,
                 const float* __restrict__ w_ek,
                 const float* __restrict__ w_k, const float* __restrict__ b_k,
                 const float* __restrict__ w_q, const float* __restrict__ b_q,
                 const float* __restrict__ w_v, const float* __restrict__ b_v,
                 const float* __restrict__ w_skip, const float* __restrict__ b_skip,
                 float* __restrict__ out)
{
    extern __shared__ float sm[];
    float* sw_k    = sm;              // 4096
    float* sw_q    = sm + 4096;       // 4096
    float* sw_v    = sm + 8192;       // 4096
    float* sw_s    = sm + 12288;      // 4096
    float* sw_ek   = sm + 16384;      // 2048
    float* sw_rbfc = sm + 18432;      // 1344
    float* sb      = sm + 19776;      // 512 (b_k,b_q,b_v,b_skip)

    for (int i = threadIdx.x; i < 4096; i += blockDim.x) {
        sw_k[i] = w_k[i]; sw_q[i] = w_q[i]; sw_v[i] = w_v[i]; sw_s[i] = w_skip[i];
    }
    for (int i = threadIdx.x; i < 2048; i += blockDim.x) sw_ek[i] = w_ek[i];
    for (int i = threadIdx.x; i < 1344; i += blockDim.x) sw_rbfc[i] = g_wrbf[i];
    for (int i = threadIdx.x; i < 128; i += blockDim.x) {
        sb[i] = b_k[i]; sb[128 + i] = b_q[i]; sb[256 + i] = b_v[i]; sb[384 + i] = b_skip[i];
    }
    __syncthreads();

    int lane = threadIdx.x & 31;
    int r = lane & 7;
    int gw = (blockIdx.x * blockDim.x + threadIdx.x) >> 5;
    int nw = (gridDim.x * blockDim.x) >> 5;

    for (int n = gw; n < NN; n += nw) {
        // rbf filter: filter[lane] = rbf[n,:] @ wrbf_c[:,lane]
        float f = 0.f;
        const float* rn = rbf + n * 42;
        #pragma unroll 6
        for (int i = 0; i < 42; i++) f = fmaf(__ldg(rn + i), sw_rbfc[i * 32 + lane], f);
        float xv = __ldg(x + n * 32 + lane);
        float xs = f * xv;

        float4 aK = *(const float4*)(sb + 4 * lane);
        float4 aQ = *(const float4*)(sb + 128 + 4 * lane);
        float4 aV = *(const float4*)(sb + 256 + 4 * lane);
        float4 aS = *(const float4*)(sb + 384 + 4 * lane);
        #pragma unroll 8
        for (int c = 0; c < 32; c++) {
            float xsc = __shfl_sync(FULL, xs, c);
            float xc  = __shfl_sync(FULL, xv, c);
            float4 wk = *(const float4*)(sw_k + c * 128 + 4 * lane);
            float4 wq = *(const float4*)(sw_q + c * 128 + 4 * lane);
            float4 wv = *(const float4*)(sw_v + c * 128 + 4 * lane);
            float4 ws = *(const float4*)(sw_s + c * 128 + 4 * lane);
            aK.x = fmaf(xsc, wk.x, aK.x); aK.y = fmaf(xsc, wk.y, aK.y);
            aK.z = fmaf(xsc, wk.z, aK.z); aK.w = fmaf(xsc, wk.w, aK.w);
            aQ.x = fmaf(xc,  wq.x, aQ.x); aQ.y = fmaf(xc,  wq.y, aQ.y);
            aQ.z = fmaf(xc,  wq.z, aQ.z); aQ.w = fmaf(xc,  wq.w, aQ.w);
            aV.x = fmaf(xsc, wv.x, aV.x); aV.y = fmaf(xsc, wv.y, aV.y);
            aV.z = fmaf(xsc, wv.z, aV.z); aV.w = fmaf(xsc, wv.w, aV.w);
            aS.x = fmaf(xc,  ws.x, aS.x); aS.y = fmaf(xc,  ws.y, aS.y);
            aS.z = fmaf(xc,  ws.z, aS.z); aS.w = fmaf(xc,  ws.w, aS.w);
        }
        *(float4*)(g_key   + n * 128 + 4 * lane) = aK;
        *(float4*)(g_query + n * 128 + 4 * lane) = aQ;
        *(float4*)(g_value + n * 128 + 4 * lane) = aV;
        *(float4*)(out     + n * 128 + 4 * lane) = aS;

        // G[n][h][i] = sum_{c in head h} w_ek[i][h*32+c] * query[h*32+c]
        float G0 = 0.f, G1 = 0.f;
        #pragma unroll
        for (int i = 0; i < 16; i++) {
            float4 we = *(const float4*)(sw_ek + i * 128 + 4 * lane);
            float p = we.x * aQ.x + we.y * aQ.y + we.z * aQ.z + we.w * aQ.w;
            p += __shfl_xor_sync(FULL, p, 1);
            p += __shfl_xor_sync(FULL, p, 2);
            p += __shfl_xor_sync(FULL, p, 4);
            if ((i >> 1) == r) { if (i & 1) G1 = p; else G0 = p; }
        }
        *(float2*)(g_G + n * 64 + (lane >> 3) * 16 + 2 * r) = make_float2(G0, G1);
    }
}

// ---------------- K2: single edge pass ----------------
// warp per edge: edge_val GEMV, gathers, alpha (q·k + ea·G), exp, sbf filter,
// unnormalized message -> vector RED into g_aggr, exp -> g_denom
__global__ __launch_bounds__(256)
void edge_kernel(const float* __restrict__ edge_attr, const float* __restrict__ sbf,
                 const float* __restrict__ w_ev, const int* __restrict__ ei)
{
    __shared__ float sw_ev[2048];
    __shared__ float sw_sf[512];
    for (int i = threadIdx.x; i < 2048; i += blockDim.x) sw_ev[i] = w_ev[i];
    for (int i = threadIdx.x; i < 512; i += blockDim.x) sw_sf[i] = g_wsbf[i];
    __syncthreads();

    int lane = threadIdx.x & 31;
    int r = lane & 7;
    int h = lane >> 3;
    int hb = lane & 24;
    int gw = (blockIdx.x * blockDim.x + threadIdx.x) >> 5;
    int nw = (gridDim.x * blockDim.x) >> 5;
    const float inv_sqrt_c = 0.17677669529663687f;  // 1/sqrt(32)

    for (int e = gw; e < EE; e += nw) {
        int src = __ldg(ei + e);
        int dst = __ldg(ei + EE + e);
        float eav = __ldg(edge_attr + e * 16 + (lane & 15));

        // edge_val[j], j = 4*lane + q
        float4 ev = make_float4(0.f, 0.f, 0.f, 0.f);
        #pragma unroll
        for (int i = 0; i < 16; i++) {
            float a = __shfl_sync(FULL, eav, i);
            float4 w = *(const float4*)(sw_ev + i * 128 + 4 * lane);
            ev.x = fmaf(a, w.x, ev.x); ev.y = fmaf(a, w.y, ev.y);
            ev.z = fmaf(a, w.z, ev.z); ev.w = fmaf(a, w.w, ev.w);
        }

        float4 kj = *(const float4*)(g_key   + src * 128 + 4 * lane);
        float4 qj = *(const float4*)(g_query + dst * 128 + 4 * lane);
        float4 vj = *(const float4*)(g_value + src * 128 + 4 * lane);
        vj.x += ev.x; vj.y += ev.y; vj.z += ev.z; vj.w += ev.w;

        // alpha = (q·key_src + ea·G[dst,h]) / sqrt(C)
        float2 G2 = *(const float2*)(g_G + dst * 64 + h * 16 + 2 * r);
        float ea0 = __shfl_sync(FULL, eav, 2 * r);
        float ea1 = __shfl_sync(FULL, eav, 2 * r + 1);
        float p = qj.x * kj.x + qj.y * kj.y + qj.z * kj.z + qj.w * kj.w
                + ea0 * G2.x + ea1 * G2.y;
        p += __shfl_xor_sync(FULL, p, 1);
        p += __shfl_xor_sync(FULL, p, 2);
        p += __shfl_xor_sync(FULL, p, 4);
        float ex = __expf(p * inv_sqrt_c);
        if (r == 0) atomicAdd(g_denom + dst * 4 + h, ex);

        // sbf filter: sf[j] = sbf[e,h,:] @ wsbf_c[:, j%32]
        float2 s2 = *(const float2*)(sbf + (size_t)e * 64 + lane * 2);
        float4 sf = make_float4(0.f, 0.f, 0.f, 0.f);
        #pragma unroll
        for (int i = 0; i < 16; i++) {
            float sv = __shfl_sync(FULL, (i & 1) ? s2.y : s2.x, hb + (i >> 1));
            float4 w = *(const float4*)(sw_sf + i * 32 + 4 * r);
            sf.x = fmaf(sv, w.x, sf.x); sf.y = fmaf(sv, w.y, sf.y);
            sf.z = fmaf(sv, w.z, sf.z); sf.w = fmaf(sv, w.w, sf.w);
        }

        float4 msg;
        msg.x = vj.x * ex * sf.x;
        msg.y = vj.y * ex * sf.y;
        msg.z = vj.z * ex * sf.z;
        msg.w = vj.w * ex * sf.w;
        atomicAdd((float4*)(g_aggr + dst * 128 + 4 * lane), msg);  // sm_90+ vector RED
    }
}

// ---------------- K3: normalize + add skip ----------------
__global__ __launch_bounds__(256)
void finalize_kernel(float* __restrict__ out)
{
    int t = blockIdx.x * blockDim.x + threadIdx.x;
    if (t >= NN * 32) return;
    int n = t >> 5;
    int g = t & 31;
    float d = g_denom[n * 4 + (g >> 3)];
    float inv = (d > 0.f) ? 1.0f / d : 0.f;
    float4 a = *(const float4*)(g_aggr + n * 128 + 4 * g);
    float4 o = *(const float4*)(out + n * 128 + 4 * g);
    o.x = fmaf(a.x, inv, o.x);
    o.y = fmaf(a.y, inv, o.y);
    o.z = fmaf(a.z, inv, o.z);
    o.w = fmaf(a.w, inv, o.w);
    *(float4*)(out + n * 128 + 4 * g) = o;
}

// ---------------- host ----------------
extern "C" void kernel_launch(void* const* d_in, const int* in_sizes, int n_in,
                              void* d_out, int out_size)
{
    const float* x         = (const float*)d_in[0];
    const float* edge_attr = (const float*)d_in[1];
    const float* rbf       = (const float*)d_in[2];
    const float* sbf       = (const float*)d_in[3];
    const float* w_rbf0    = (const float*)d_in[4];
    const float* w_rbf1    = (const float*)d_in[5];
    const float* w_sbf0    = (const float*)d_in[6];
    const float* w_sbf1    = (const float*)d_in[7];
    const float* w_ek      = (const float*)d_in[8];
    const float* w_ev      = (const float*)d_in[9];
    const float* w_k       = (const float*)d_in[10];
    const float* b_k       = (const float*)d_in[11];
    const float* w_q       = (const float*)d_in[12];
    const float* b_q       = (const float*)d_in[13];
    const float* w_v       = (const float*)d_in[14];
    const float* b_v       = (const float*)d_in[15];
    const float* w_skip    = (const float*)d_in[16];
    const float* b_skip    = (const float*)d_in[17];
    const int*   ei        = (const int*)d_in[18];
    float* out = (float*)d_out;

    void* p_aggr = nullptr; void* p_denom = nullptr;
    cudaGetSymbolAddress(&p_aggr, g_aggr);
    cudaGetSymbolAddress(&p_denom, g_denom);
    cudaMemsetAsync(p_aggr, 0, (size_t)NN * 128 * sizeof(float));
    cudaMemsetAsync(p_denom, 0, (size_t)NN * 4 * sizeof(float));

    combine_weights_kernel<<<6, 256>>>(w_rbf0, w_rbf1, w_sbf0, w_sbf1);

    int smem = 20288 * (int)sizeof(float);  // 81152 B
    cudaFuncSetAttribute(node_kernel, cudaFuncAttributeMaxDynamicSharedMemorySize, smem);
    node_kernel<<<740, 256, smem>>>(x, rbf, w_ek, w_k, b_k, w_q, b_q,
                                    w_v, b_v, w_skip, b_skip, out);

    edge_kernel<<<2960, 256>>>(edge_attr, sbf, w_ev, ei);

    finalize_kernel<<<(NN * 32 + 255) / 256, 256>>>(out);
}

// round 6
// speedup vs baseline: 1.4220x; 1.4220x over previous
#include <cuda_runtime.h>

#define NN 100000
#define EE 800000
#define FULL 0xffffffffu

// ---------------- device scratch (no allocs allowed) ----------------
__device__ float g_key[NN * 128];
__device__ float g_query[NN * 128];
__device__ float g_value[NN * 128];
__device__ float g_aggr[NN * 128];
__device__ float g_G[NN * 64];     // [n][h][i] : per-node folded w_ek·query
__device__ float g_denom[NN * 4];
__device__ float g_wrbf[42 * 32];  // w_rbf0 @ w_rbf1
__device__ float g_wsbf[16 * 32];  // w_sbf0 @ w_sbf1

// ---------------- K0: fold weight pairs ----------------
__global__ void combine_weights_kernel(const float* __restrict__ w_rbf0,
                                       const float* __restrict__ w_rbf1,
                                       const float* __restrict__ w_sbf0,
                                       const float* __restrict__ w_sbf1)
{
    int t = blockIdx.x * blockDim.x + threadIdx.x;
    if (t < 42 * 32) {
        int i = t >> 5, o = t & 31;
        float s = 0.f;
        #pragma unroll
        for (int k = 0; k < 32; k++) s = fmaf(w_rbf0[i * 32 + k], w_rbf1[k * 32 + o], s);
        g_wrbf[t] = s;
    }
    if (t < 16 * 32) {
        int i = t >> 5, o = t & 31;
        float s = 0.f;
        #pragma unroll
        for (int k = 0; k < 32; k++) s = fmaf(w_sbf0[i * 32 + k], w_sbf1[k * 32 + o], s);
        g_wsbf[t] = s;
    }
}

// ---------------- K1: per-node key/query/value/skip + G ----------------
// one warp per 2 nodes per iteration; weight LDS amortized across the pair
__global__ __launch_bounds__(256)
void node_kernel(const float* __restrict__ x, const float* __restrict__ rbf,
                 const float* __restrict__ w_ek,
                 const float* __restrict__ w_k, const float* __restrict__ b_k,
                 const float* __restrict__ w_q, const float* __restrict__ b_q,
                 const float* __restrict__ w_v, const float* __restrict__ b_v,
                 const float* __restrict__ w_skip, const float* __restrict__ b_skip,
                 float* __restrict__ out)
{
    extern __shared__ float sm[];
    float* sw_k    = sm;              // 4096
    float* sw_q    = sm + 4096;       // 4096
    float* sw_v    = sm + 8192;       // 4096
    float* sw_s    = sm + 12288;      // 4096
    float* sw_ek   = sm + 16384;      // 2048
    float* sw_rbfc = sm + 18432;      // 1344
    float* sb      = sm + 19776;      // 512 (b_k,b_q,b_v,b_skip)

    for (int i = threadIdx.x; i < 4096; i += blockDim.x) {
        sw_k[i] = w_k[i]; sw_q[i] = w_q[i]; sw_v[i] = w_v[i]; sw_s[i] = w_skip[i];
    }
    for (int i = threadIdx.x; i < 2048; i += blockDim.x) sw_ek[i] = w_ek[i];
    for (int i = threadIdx.x; i < 1344; i += blockDim.x) sw_rbfc[i] = g_wrbf[i];
    for (int i = threadIdx.x; i < 128; i += blockDim.x) {
        sb[i] = b_k[i]; sb[128 + i] = b_q[i]; sb[256 + i] = b_v[i]; sb[384 + i] = b_skip[i];
    }
    __syncthreads();

    int lane = threadIdx.x & 31;
    int r = lane & 7;
    int gw = (blockIdx.x * blockDim.x + threadIdx.x) >> 5;
    int nw = (gridDim.x * blockDim.x) >> 5;

    // NN is even: every pair (n, n+1) is full
    for (int n0 = gw * 2; n0 < NN; n0 += nw * 2) {
        int n1 = n0 + 1;

        // rbf filters for both nodes
        float f0 = 0.f, f1 = 0.f;
        const float* rn0 = rbf + n0 * 42;
        const float* rn1 = rbf + n1 * 42;
        #pragma unroll 6
        for (int i = 0; i < 42; i++) {
            float w = sw_rbfc[i * 32 + lane];
            f0 = fmaf(__ldg(rn0 + i), w, f0);
            f1 = fmaf(__ldg(rn1 + i), w, f1);
        }
        float xv0 = __ldg(x + n0 * 32 + lane);
        float xv1 = __ldg(x + n1 * 32 + lane);
        float xs0 = f0 * xv0;
        float xs1 = f1 * xv1;

        float4 bK = *(const float4*)(sb + 4 * lane);
        float4 bQ = *(const float4*)(sb + 128 + 4 * lane);
        float4 bV = *(const float4*)(sb + 256 + 4 * lane);
        float4 bS = *(const float4*)(sb + 384 + 4 * lane);
        float4 aK0 = bK, aK1 = bK;
        float4 aQ0 = bQ, aQ1 = bQ;
        float4 aV0 = bV, aV1 = bV;
        float4 aS0 = bS, aS1 = bS;

        #pragma unroll 8
        for (int c = 0; c < 32; c++) {
            float xsc0 = __shfl_sync(FULL, xs0, c);
            float xc0  = __shfl_sync(FULL, xv0, c);
            float xsc1 = __shfl_sync(FULL, xs1, c);
            float xc1  = __shfl_sync(FULL, xv1, c);
            float4 wk = *(const float4*)(sw_k + c * 128 + 4 * lane);
            float4 wq = *(const float4*)(sw_q + c * 128 + 4 * lane);
            float4 wv = *(const float4*)(sw_v + c * 128 + 4 * lane);
            float4 ws = *(const float4*)(sw_s + c * 128 + 4 * lane);
            aK0.x = fmaf(xsc0, wk.x, aK0.x); aK0.y = fmaf(xsc0, wk.y, aK0.y);
            aK0.z = fmaf(xsc0, wk.z, aK0.z); aK0.w = fmaf(xsc0, wk.w, aK0.w);
            aK1.x = fmaf(xsc1, wk.x, aK1.x); aK1.y = fmaf(xsc1, wk.y, aK1.y);
            aK1.z = fmaf(xsc1, wk.z, aK1.z); aK1.w = fmaf(xsc1, wk.w, aK1.w);
            aQ0.x = fmaf(xc0,  wq.x, aQ0.x); aQ0.y = fmaf(xc0,  wq.y, aQ0.y);
            aQ0.z = fmaf(xc0,  wq.z, aQ0.z); aQ0.w = fmaf(xc0,  wq.w, aQ0.w);
            aQ1.x = fmaf(xc1,  wq.x, aQ1.x); aQ1.y = fmaf(xc1,  wq.y, aQ1.y);
            aQ1.z = fmaf(xc1,  wq.z, aQ1.z); aQ1.w = fmaf(xc1,  wq.w, aQ1.w);
            aV0.x = fmaf(xsc0, wv.x, aV0.x); aV0.y = fmaf(xsc0, wv.y, aV0.y);
            aV0.z = fmaf(xsc0, wv.z, aV0.z); aV0.w = fmaf(xsc0, wv.w, aV0.w);
            aV1.x = fmaf(xsc1, wv.x, aV1.x); aV1.y = fmaf(xsc1, wv.y, aV1.y);
            aV1.z = fmaf(xsc1, wv.z, aV1.z); aV1.w = fmaf(xsc1, wv.w, aV1.w);
            aS0.x = fmaf(xc0,  ws.x, aS0.x); aS0.y = fmaf(xc0,  ws.y, aS0.y);
            aS0.z = fmaf(xc0,  ws.z, aS0.z); aS0.w = fmaf(xc0,  ws.w, aS0.w);
            aS1.x = fmaf(xc1,  ws.x, aS1.x); aS1.y = fmaf(xc1,  ws.y, aS1.y);
            aS1.z = fmaf(xc1,  ws.z, aS1.z); aS1.w = fmaf(xc1,  ws.w, aS1.w);
        }
        *(float4*)(g_key   + n0 * 128 + 4 * lane) = aK0;
        *(float4*)(g_key   + n1 * 128 + 4 * lane) = aK1;
        *(float4*)(g_query + n0 * 128 + 4 * lane) = aQ0;
        *(float4*)(g_query + n1 * 128 + 4 * lane) = aQ1;
        *(float4*)(g_value + n0 * 128 + 4 * lane) = aV0;
        *(float4*)(g_value + n1 * 128 + 4 * lane) = aV1;
        *(float4*)(out     + n0 * 128 + 4 * lane) = aS0;
        *(float4*)(out     + n1 * 128 + 4 * lane) = aS1;

        // G[n][h][i] = sum_{c in head h} w_ek[i][h*32+c] * query[h*32+c]
        float G00 = 0.f, G01 = 0.f, G10 = 0.f, G11 = 0.f;
        #pragma unroll
        for (int i = 0; i < 16; i++) {
            float4 we = *(const float4*)(sw_ek + i * 128 + 4 * lane);
            float p0 = we.x * aQ0.x + we.y * aQ0.y + we.z * aQ0.z + we.w * aQ0.w;
            float p1 = we.x * aQ1.x + we.y * aQ1.y + we.z * aQ1.z + we.w * aQ1.w;
            p0 += __shfl_xor_sync(FULL, p0, 1);
            p0 += __shfl_xor_sync(FULL, p0, 2);
            p0 += __shfl_xor_sync(FULL, p0, 4);
            p1 += __shfl_xor_sync(FULL, p1, 1);
            p1 += __shfl_xor_sync(FULL, p1, 2);
            p1 += __shfl_xor_sync(FULL, p1, 4);
            if ((i >> 1) == r) {
                if (i & 1) { G01 = p0; G11 = p1; }
                else       { G00 = p0; G10 = p1; }
            }
        }
        *(float2*)(g_G + n0 * 64 + (lane >> 3) * 16 + 2 * r) = make_float2(G00, G01);
        *(float2*)(g_G + n1 * 64 + (lane >> 3) * 16 + 2 * r) = make_float2(G10, G11);
    }
}

// ---------------- K2: single edge pass (2 edges per warp iteration) ----------------
__global__ __launch_bounds__(256)
void edge_kernel(const float* __restrict__ edge_attr, const float* __restrict__ sbf,
                 const float* __restrict__ w_ev, const int* __restrict__ ei)
{
    __shared__ float sw_ev[2048];
    __shared__ float sw_sf[512];
    for (int i = threadIdx.x; i < 2048; i += blockDim.x) sw_ev[i] = w_ev[i];
    for (int i = threadIdx.x; i < 512; i += blockDim.x) sw_sf[i] = g_wsbf[i];
    __syncthreads();

    int lane = threadIdx.x & 31;
    int r = lane & 7;
    int h = lane >> 3;
    int hb = lane & 24;
    int gw = (blockIdx.x * blockDim.x + threadIdx.x) >> 5;
    int nw = (gridDim.x * blockDim.x) >> 5;
    const float inv_sqrt_c = 0.17677669529663687f;  // 1/sqrt(32)

    // EE even: every pair (e, e+1) is full
    for (int e = gw * 2; e < EE; e += nw * 2) {
        int s0 = __ldg(ei + e);
        int s1 = __ldg(ei + e + 1);
        int d0 = __ldg(ei + EE + e);
        int d1 = __ldg(ei + EE + e + 1);
        float ea0v = __ldg(edge_attr + (size_t)e * 16 + (lane & 15));
        float ea1v = __ldg(edge_attr + (size_t)(e + 1) * 16 + (lane & 15));

        // edge_val GEMV for both edges, sharing the weight LDS
        float4 ev0 = make_float4(0.f, 0.f, 0.f, 0.f);
        float4 ev1 = make_float4(0.f, 0.f, 0.f, 0.f);
        #pragma unroll
        for (int i = 0; i < 16; i++) {
            float a0 = __shfl_sync(FULL, ea0v, i);
            float a1 = __shfl_sync(FULL, ea1v, i);
            float4 w = *(const float4*)(sw_ev + i * 128 + 4 * lane);
            ev0.x = fmaf(a0, w.x, ev0.x); ev0.y = fmaf(a0, w.y, ev0.y);
            ev0.z = fmaf(a0, w.z, ev0.z); ev0.w = fmaf(a0, w.w, ev0.w);
            ev1.x = fmaf(a1, w.x, ev1.x); ev1.y = fmaf(a1, w.y, ev1.y);
            ev1.z = fmaf(a1, w.z, ev1.z); ev1.w = fmaf(a1, w.w, ev1.w);
        }

        // gathers (independent -> MLP)
        float4 k0 = *(const float4*)(g_key   + (size_t)s0 * 128 + 4 * lane);
        float4 k1 = *(const float4*)(g_key   + (size_t)s1 * 128 + 4 * lane);
        float4 q0 = *(const float4*)(g_query + (size_t)d0 * 128 + 4 * lane);
        float4 q1 = *(const float4*)(g_query + (size_t)d1 * 128 + 4 * lane);
        float4 v0 = *(const float4*)(g_value + (size_t)s0 * 128 + 4 * lane);
        float4 v1 = *(const float4*)(g_value + (size_t)s1 * 128 + 4 * lane);
        v0.x += ev0.x; v0.y += ev0.y; v0.z += ev0.z; v0.w += ev0.w;
        v1.x += ev1.x; v1.y += ev1.y; v1.z += ev1.z; v1.w += ev1.w;

        float2 Ga = *(const float2*)(g_G + (size_t)d0 * 64 + h * 16 + 2 * r);
        float2 Gb = *(const float2*)(g_G + (size_t)d1 * 64 + h * 16 + 2 * r);
        float e00 = __shfl_sync(FULL, ea0v, 2 * r);
        float e01 = __shfl_sync(FULL, ea0v, 2 * r + 1);
        float e10 = __shfl_sync(FULL, ea1v, 2 * r);
        float e11 = __shfl_sync(FULL, ea1v, 2 * r + 1);
        float p0 = q0.x * k0.x + q0.y * k0.y + q0.z * k0.z + q0.w * k0.w
                 + e00 * Ga.x + e01 * Ga.y;
        float p1 = q1.x * k1.x + q1.y * k1.y + q1.z * k1.z + q1.w * k1.w
                 + e10 * Gb.x + e11 * Gb.y;
        p0 += __shfl_xor_sync(FULL, p0, 1);
        p0 += __shfl_xor_sync(FULL, p0, 2);
        p0 += __shfl_xor_sync(FULL, p0, 4);
        p1 += __shfl_xor_sync(FULL, p1, 1);
        p1 += __shfl_xor_sync(FULL, p1, 2);
        p1 += __shfl_xor_sync(FULL, p1, 4);
        float ex0 = __expf(p0 * inv_sqrt_c);
        float ex1 = __expf(p1 * inv_sqrt_c);
        if (r == 0) {
            atomicAdd(g_denom + (size_t)d0 * 4 + h, ex0);
            atomicAdd(g_denom + (size_t)d1 * 4 + h, ex1);
        }

        // sbf filters, sharing the weight LDS (broadcast-friendly addressing)
        float2 sa = *(const float2*)(sbf + (size_t)e * 64 + lane * 2);
        float2 sb2 = *(const float2*)(sbf + (size_t)(e + 1) * 64 + lane * 2);
        float4 sf0 = make_float4(0.f, 0.f, 0.f, 0.f);
        float4 sf1 = make_float4(0.f, 0.f, 0.f, 0.f);
        #pragma unroll
        for (int i = 0; i < 16; i++) {
            float sv0 = __shfl_sync(FULL, (i & 1) ? sa.y  : sa.x,  hb + (i >> 1));
            float sv1 = __shfl_sync(FULL, (i & 1) ? sb2.y : sb2.x, hb + (i >> 1));
            float4 w = *(const float4*)(sw_sf + i * 32 + 4 * r);
            sf0.x = fmaf(sv0, w.x, sf0.x); sf0.y = fmaf(sv0, w.y, sf0.y);
            sf0.z = fmaf(sv0, w.z, sf0.z); sf0.w = fmaf(sv0, w.w, sf0.w);
            sf1.x = fmaf(sv1, w.x, sf1.x); sf1.y = fmaf(sv1, w.y, sf1.y);
            sf1.z = fmaf(sv1, w.z, sf1.z); sf1.w = fmaf(sv1, w.w, sf1.w);
        }

        float4 m0, m1;
        m0.x = v0.x * ex0 * sf0.x; m0.y = v0.y * ex0 * sf0.y;
        m0.z = v0.z * ex0 * sf0.z; m0.w = v0.w * ex0 * sf0.w;
        m1.x = v1.x * ex1 * sf1.x; m1.y = v1.y * ex1 * sf1.y;
        m1.z = v1.z * ex1 * sf1.z; m1.w = v1.w * ex1 * sf1.w;
        atomicAdd((float4*)(g_aggr + (size_t)d0 * 128 + 4 * lane), m0);
        atomicAdd((float4*)(g_aggr + (size_t)d1 * 128 + 4 * lane), m1);
    }
}

// ---------------- K3: normalize + add skip ----------------
__global__ __launch_bounds__(256)
void finalize_kernel(float* __restrict__ out)
{
    int t = blockIdx.x * blockDim.x + threadIdx.x;
    if (t >= NN * 32) return;
    int n = t >> 5;
    int g = t & 31;
    float d = g_denom[n * 4 + (g >> 3)];
    float inv = (d > 0.f) ? 1.0f / d : 0.f;
    float4 a = *(const float4*)(g_aggr + n * 128 + 4 * g);
    float4 o = *(const float4*)(out + n * 128 + 4 * g);
    o.x = fmaf(a.x, inv, o.x);
    o.y = fmaf(a.y, inv, o.y);
    o.z = fmaf(a.z, inv, o.z);
    o.w = fmaf(a.w, inv, o.w);
    *(float4*)(out + n * 128 + 4 * g) = o;
}

// ---------------- host ----------------
extern "C" void kernel_launch(void* const* d_in, const int* in_sizes, int n_in,
                              void* d_out, int out_size)
{
    const float* x         = (const float*)d_in[0];
    const float* edge_attr = (const float*)d_in[1];
    const float* rbf       = (const float*)d_in[2];
    const float* sbf       = (const float*)d_in[3];
    const float* w_rbf0    = (const float*)d_in[4];
    const float* w_rbf1    = (const float*)d_in[5];
    const float* w_sbf0    = (const float*)d_in[6];
    const float* w_sbf1    = (const float*)d_in[7];
    const float* w_ek      = (const float*)d_in[8];
    const float* w_ev      = (const float*)d_in[9];
    const float* w_k       = (const float*)d_in[10];
    const float* b_k       = (const float*)d_in[11];
    const float* w_q       = (const float*)d_in[12];
    const float* b_q       = (const float*)d_in[13];
    const float* w_v       = (const float*)d_in[14];
    const float* b_v       = (const float*)d_in[15];
    const float* w_skip    = (const float*)d_in[16];
    const float* b_skip    = (const float*)d_in[17];
    const int*   ei        = (const int*)d_in[18];
    float* out = (float*)d_out;

    void* p_aggr = nullptr; void* p_denom = nullptr;
    cudaGetSymbolAddress(&p_aggr, g_aggr);
    cudaGetSymbolAddress(&p_denom, g_denom);
    cudaMemsetAsync(p_aggr, 0, (size_t)NN * 128 * sizeof(float));
    cudaMemsetAsync(p_denom, 0, (size_t)NN * 4 * sizeof(float));

    combine_weights_kernel<<<6, 256>>>(w_rbf0, w_rbf1, w_sbf0, w_sbf1);

    int smem = 20288 * (int)sizeof(float);  // 81152 B -> 2 CTA/SM
    cudaFuncSetAttribute(node_kernel, cudaFuncAttributeMaxDynamicSharedMemorySize, smem);
    node_kernel<<<296, 256, smem>>>(x, rbf, w_ek, w_k, b_k, w_q, b_q,
                                    w_v, b_v, w_skip, b_skip, out);

    edge_kernel<<<1184, 256>>>(edge_attr, sbf, w_ev, ei);

    finalize_kernel<<<(NN * 32 + 255) / 256, 256>>>(out);
}

// round 8
// speedup vs baseline: 1.5542x; 1.0930x over previous
#include <cuda_runtime.h>

#define NN 100000
#define EE 800000
#define FULL 0xffffffffu

typedef unsigned long long u64t;

// ---- f32x2 packed-math helpers (Blackwell FFMA2 path, PTX-only) ----
__device__ __forceinline__ u64t pk2(float lo, float hi) {
    u64t r; asm("mov.b64 %0, {%1, %2};" : "=l"(r) : "f"(lo), "f"(hi)); return r;
}
__device__ __forceinline__ void up2(float& lo, float& hi, u64t v) {
    asm("mov.b64 {%0, %1}, %2;" : "=f"(lo), "=f"(hi) : "l"(v));
}
__device__ __forceinline__ u64t fma2_(u64t a, u64t b, u64t c) {
    u64t d; asm("fma.rn.f32x2 %0, %1, %2, %3;" : "=l"(d) : "l"(a), "l"(b), "l"(c)); return d;
}
__device__ __forceinline__ u64t mul2_(u64t a, u64t b) {
    u64t d; asm("mul.rn.f32x2 %0, %1, %2;" : "=l"(d) : "l"(a), "l"(b)); return d;
}
__device__ __forceinline__ u64t add2_(u64t a, u64t b) {
    u64t d; asm("add.rn.f32x2 %0, %1, %2;" : "=l"(d) : "l"(a), "l"(b)); return d;
}
// static component select (folds when k is a compile-time constant)
__device__ __forceinline__ float c4(const float4 v, int k) {
    return k == 0 ? v.x : k == 1 ? v.y : k == 2 ? v.z : v.w;
}

// ---------------- device scratch (no allocs allowed) ----------------
__device__ float g_key[NN * 128];
__device__ float g_query[NN * 128];
__device__ float g_value[NN * 128];
__device__ float g_aggr[NN * 128];
__device__ float g_G[NN * 64];
__device__ float g_denom[NN * 4];
__device__ float g_wrbf[42 * 32];
__device__ float g_wsbf[16 * 32];

// ---------------- K0: fold weight pairs ----------------
__global__ void combine_weights_kernel(const float* __restrict__ w_rbf0,
                                       const float* __restrict__ w_rbf1,
                                       const float* __restrict__ w_sbf0,
                                       const float* __restrict__ w_sbf1)
{
    int t = blockIdx.x * blockDim.x + threadIdx.x;
    if (t < 42 * 32) {
        int i = t >> 5, o = t & 31;
        float s = 0.f;
        #pragma unroll
        for (int k = 0; k < 32; k++) s = fmaf(w_rbf0[i * 32 + k], w_rbf1[k * 32 + o], s);
        g_wrbf[t] = s;
    }
    if (t < 16 * 32) {
        int i = t >> 5, o = t & 31;
        float s = 0.f;
        #pragma unroll
        for (int k = 0; k < 32; k++) s = fmaf(w_sbf0[i * 32 + k], w_sbf1[k * 32 + o], s);
        g_wsbf[t] = s;
    }
}

// ---------------- K1: per-node K/Q/V/skip + G, 4 nodes per warp iter ----------------
__global__ __launch_bounds__(256, 2)
void node_kernel(const float* __restrict__ x, const float* __restrict__ rbf,
                 const float* __restrict__ w_ek,
                 const float* __restrict__ w_k, const float* __restrict__ b_k,
                 const float* __restrict__ w_q, const float* __restrict__ b_q,
                 const float* __restrict__ w_v, const float* __restrict__ b_v,
                 const float* __restrict__ w_skip, const float* __restrict__ b_skip,
                 float* __restrict__ out)
{
    extern __shared__ float sm[];
    float* sw_k    = sm;              // 4096
    float* sw_q    = sm + 4096;       // 4096
    float* sw_v    = sm + 8192;       // 4096
    float* sw_s    = sm + 12288;      // 4096
    float* sw_ek   = sm + 16384;      // 2048
    float* sw_rbfc = sm + 18432;      // 1344
    float* sb      = sm + 19776;      // 512

    for (int i = threadIdx.x; i < 4096; i += blockDim.x) {
        sw_k[i] = w_k[i]; sw_q[i] = w_q[i]; sw_v[i] = w_v[i]; sw_s[i] = w_skip[i];
    }
    for (int i = threadIdx.x; i < 2048; i += blockDim.x) sw_ek[i] = w_ek[i];
    for (int i = threadIdx.x; i < 1344; i += blockDim.x) sw_rbfc[i] = g_wrbf[i];
    for (int i = threadIdx.x; i < 128; i += blockDim.x) {
        sb[i] = b_k[i]; sb[128 + i] = b_q[i]; sb[256 + i] = b_v[i]; sb[384 + i] = b_skip[i];
    }
    __syncthreads();

    int lane = threadIdx.x & 31;
    int r = lane & 7;
    int gw = (blockIdx.x * blockDim.x + threadIdx.x) >> 5;
    int nw = (gridDim.x * blockDim.x) >> 5;

    // NN % 4 == 0: every group of 4 is full
    for (int n0 = gw * 4; n0 < NN; n0 += nw * 4) {
        // rbf filters for 4 nodes
        float f[4] = {0.f, 0.f, 0.f, 0.f};
        const float* rn = rbf + (size_t)n0 * 42;
        #pragma unroll 6
        for (int i = 0; i < 42; i++) {
            float w = sw_rbfc[i * 32 + lane];
            f[0] = fmaf(__ldg(rn + i),       w, f[0]);
            f[1] = fmaf(__ldg(rn + 42 + i),  w, f[1]);
            f[2] = fmaf(__ldg(rn + 84 + i),  w, f[2]);
            f[3] = fmaf(__ldg(rn + 126 + i), w, f[3]);
        }
        float xv[4], xs[4];
        #pragma unroll
        for (int j = 0; j < 4; j++) {
            xv[j] = __ldg(x + (size_t)(n0 + j) * 32 + lane);
            xs[j] = f[j] * xv[j];
        }

        ulonglong2 bK = *(const ulonglong2*)(sb + 4 * lane);
        ulonglong2 bQ = *(const ulonglong2*)(sb + 128 + 4 * lane);
        ulonglong2 bV = *(const ulonglong2*)(sb + 256 + 4 * lane);
        ulonglong2 bS = *(const ulonglong2*)(sb + 384 + 4 * lane);
        u64t aK[4][2], aQ[4][2], aV[4][2], aS[4][2];
        #pragma unroll
        for (int j = 0; j < 4; j++) {
            aK[j][0] = bK.x; aK[j][1] = bK.y;
            aQ[j][0] = bQ.x; aQ[j][1] = bQ.y;
            aV[j][0] = bV.x; aV[j][1] = bV.y;
            aS[j][0] = bS.x; aS[j][1] = bS.y;
        }

        #pragma unroll 8
        for (int c = 0; c < 32; c++) {
            ulonglong2 wk = *(const ulonglong2*)(sw_k + c * 128 + 4 * lane);
            ulonglong2 wq = *(const ulonglong2*)(sw_q + c * 128 + 4 * lane);
            ulonglong2 wv = *(const ulonglong2*)(sw_v + c * 128 + 4 * lane);
            ulonglong2 ws = *(const ulonglong2*)(sw_s + c * 128 + 4 * lane);
            #pragma unroll
            for (int j = 0; j < 4; j++) {
                float ms = __shfl_sync(FULL, xs[j], c);
                float mx = __shfl_sync(FULL, xv[j], c);
                u64t pms = pk2(ms, ms);
                u64t pmx = pk2(mx, mx);
                aK[j][0] = fma2_(pms, wk.x, aK[j][0]); aK[j][1] = fma2_(pms, wk.y, aK[j][1]);
                aQ[j][0] = fma2_(pmx, wq.x, aQ[j][0]); aQ[j][1] = fma2_(pmx, wq.y, aQ[j][1]);
                aV[j][0] = fma2_(pms, wv.x, aV[j][0]); aV[j][1] = fma2_(pms, wv.y, aV[j][1]);
                aS[j][0] = fma2_(pmx, ws.x, aS[j][0]); aS[j][1] = fma2_(pmx, ws.y, aS[j][1]);
            }
        }

        #pragma unroll
        for (int j = 0; j < 4; j++) {
            ulonglong2 o;
            o.x = aK[j][0]; o.y = aK[j][1];
            *(ulonglong2*)(g_key   + (size_t)(n0 + j) * 128 + 4 * lane) = o;
            o.x = aQ[j][0]; o.y = aQ[j][1];
            *(ulonglong2*)(g_query + (size_t)(n0 + j) * 128 + 4 * lane) = o;
            o.x = aV[j][0]; o.y = aV[j][1];
            *(ulonglong2*)(g_value + (size_t)(n0 + j) * 128 + 4 * lane) = o;
            o.x = aS[j][0]; o.y = aS[j][1];
            *(ulonglong2*)(out     + (size_t)(n0 + j) * 128 + 4 * lane) = o;
        }

        // G[n][h][i] = sum_{c in head h} w_ek[i][h*32+c] * query[h*32+c]
        float4 q[4];
        #pragma unroll
        for (int j = 0; j < 4; j++) {
            up2(q[j].x, q[j].y, aQ[j][0]);
            up2(q[j].z, q[j].w, aQ[j][1]);
        }
        float G0[4] = {0.f,0.f,0.f,0.f}, G1[4] = {0.f,0.f,0.f,0.f};
        #pragma unroll
        for (int i = 0; i < 16; i++) {
            float4 we = *(const float4*)(sw_ek + i * 128 + 4 * lane);
            #pragma unroll
            for (int j = 0; j < 4; j++) {
                float p = we.x * q[j].x + we.y * q[j].y + we.z * q[j].z + we.w * q[j].w;
                p += __shfl_xor_sync(FULL, p, 1);
                p += __shfl_xor_sync(FULL, p, 2);
                p += __shfl_xor_sync(FULL, p, 4);
                if ((i >> 1) == r) { if (i & 1) G1[j] = p; else G0[j] = p; }
            }
        }
        #pragma unroll
        for (int j = 0; j < 4; j++)
            *(float2*)(g_G + (size_t)(n0 + j) * 64 + (lane >> 3) * 16 + 2 * r)
                = make_float2(G0[j], G1[j]);
    }
}

// ---------------- K2: edge pass, 2 edges/iter, shuffle-free GEMVs ----------------
__global__ __launch_bounds__(256, 2)
void edge_kernel(const float* __restrict__ edge_attr, const float* __restrict__ sbf,
                 const float* __restrict__ w_ev, const int* __restrict__ ei)
{
    __shared__ __align__(16) float sw_ev[2048];
    __shared__ __align__(16) float sw_sf[512];
    for (int i = threadIdx.x; i < 2048; i += blockDim.x) sw_ev[i] = w_ev[i];
    for (int i = threadIdx.x; i < 512; i += blockDim.x) sw_sf[i] = g_wsbf[i];
    __syncthreads();

    int lane = threadIdx.x & 31;
    int r = lane & 7;
    int h = lane >> 3;
    int gw = (blockIdx.x * blockDim.x + threadIdx.x) >> 5;
    int nw = (gridDim.x * blockDim.x) >> 5;
    const float inv_sqrt_c = 0.17677669529663687f;

    for (int e = gw * 2; e < EE; e += nw * 2) {
        int s0 = __ldg(ei + e);
        int s1 = __ldg(ei + e + 1);
        int d0 = __ldg(ei + EE + e);
        int d1 = __ldg(ei + EE + e + 1);

        // full edge_attr rows in registers (uniform-address LDG.128, L1 broadcast)
        const float4* eap = (const float4*)(edge_attr + (size_t)e * 16);
        float4 ea0[4], ea1[4];
        #pragma unroll
        for (int i = 0; i < 4; i++) { ea0[i] = __ldg(eap + i); ea1[i] = __ldg(eap + 4 + i); }
        // per-lane scalar (lanes 0..15 distinct) for the alpha broadcast below
        float eav0 = __ldg(edge_attr + (size_t)e * 16 + (lane & 15));
        float eav1 = __ldg(edge_attr + (size_t)(e + 1) * 16 + (lane & 15));

        // edge_val GEMV, shuffle-free, f32x2
        u64t ev0l = 0, ev0h = 0, ev1l = 0, ev1h = 0;
        #pragma unroll
        for (int i = 0; i < 16; i++) {
            float a0 = c4(ea0[i >> 2], i & 3);
            float a1 = c4(ea1[i >> 2], i & 3);
            ulonglong2 w = *(const ulonglong2*)(sw_ev + i * 128 + 4 * lane);
            u64t pa0 = pk2(a0, a0);
            u64t pa1 = pk2(a1, a1);
            ev0l = fma2_(pa0, w.x, ev0l); ev0h = fma2_(pa0, w.y, ev0h);
            ev1l = fma2_(pa1, w.x, ev1l); ev1h = fma2_(pa1, w.y, ev1h);
        }

        // gathers
        ulonglong2 k0 = *(const ulonglong2*)(g_key   + (size_t)s0 * 128 + 4 * lane);
        ulonglong2 k1 = *(const ulonglong2*)(g_key   + (size_t)s1 * 128 + 4 * lane);
        ulonglong2 q0 = *(const ulonglong2*)(g_query + (size_t)d0 * 128 + 4 * lane);
        ulonglong2 q1 = *(const ulonglong2*)(g_query + (size_t)d1 * 128 + 4 * lane);
        ulonglong2 v0 = *(const ulonglong2*)(g_value + (size_t)s0 * 128 + 4 * lane);
        ulonglong2 v1 = *(const ulonglong2*)(g_value + (size_t)s1 * 128 + 4 * lane);
        float2 Ga = *(const float2*)(g_G + (size_t)d0 * 64 + h * 16 + 2 * r);
        float2 Gb = *(const float2*)(g_G + (size_t)d1 * 64 + h * 16 + 2 * r);

        // alpha
        float e00 = __shfl_sync(FULL, eav0, 2 * r);
        float e01 = __shfl_sync(FULL, eav0, 2 * r + 1);
        float e10 = __shfl_sync(FULL, eav1, 2 * r);
        float e11 = __shfl_sync(FULL, eav1, 2 * r + 1);
        u64t t0 = fma2_(q0.x, k0.x, mul2_(q0.y, k0.y));
        u64t t1 = fma2_(q1.x, k1.x, mul2_(q1.y, k1.y));
        float tl, th;
        up2(tl, th, t0);
        float p0 = tl + th + e00 * Ga.x + e01 * Ga.y;
        up2(tl, th, t1);
        float p1 = tl + th + e10 * Gb.x + e11 * Gb.y;
        p0 += __shfl_xor_sync(FULL, p0, 1);
        p0 += __shfl_xor_sync(FULL, p0, 2);
        p0 += __shfl_xor_sync(FULL, p0, 4);
        p1 += __shfl_xor_sync(FULL, p1, 1);
        p1 += __shfl_xor_sync(FULL, p1, 2);
        p1 += __shfl_xor_sync(FULL, p1, 4);
        float ex0 = __expf(p0 * inv_sqrt_c);
        float ex1 = __expf(p1 * inv_sqrt_c);
        if (r == 0) {
            atomicAdd(g_denom + (size_t)d0 * 4 + h, ex0);
            atomicAdd(g_denom + (size_t)d1 * 4 + h, ex1);
        }

        // sbf rows for this lane's head, in registers (segment LDG.128)
        const float4* sp0 = (const float4*)(sbf + (size_t)e * 64 + h * 16);
        float4 sb0[4], sb1[4];
        #pragma unroll
        for (int i = 0; i < 4; i++) { sb0[i] = __ldg(sp0 + i); sb1[i] = __ldg(sp0 + 16 + i); }

        // sbf filter GEMV, shuffle-free, f32x2
        u64t sf0l = 0, sf0h = 0, sf1l = 0, sf1h = 0;
        #pragma unroll
        for (int i = 0; i < 16; i++) {
            float a0 = c4(sb0[i >> 2], i & 3);
            float a1 = c4(sb1[i >> 2], i & 3);
            ulonglong2 w = *(const ulonglong2*)(sw_sf + i * 32 + 4 * r);
            u64t pa0 = pk2(a0, a0);
            u64t pa1 = pk2(a1, a1);
            sf0l = fma2_(pa0, w.x, sf0l); sf0h = fma2_(pa0, w.y, sf0h);
            sf1l = fma2_(pa1, w.x, sf1l); sf1h = fma2_(pa1, w.y, sf1h);
        }

        // message = (value + edge_val) * ex * sf
        u64t pex0 = pk2(ex0, ex0);
        u64t pex1 = pk2(ex1, ex1);
        u64t m0l = mul2_(mul2_(add2_(v0.x, ev0l), sf0l), pex0);
        u64t m0h = mul2_(mul2_(add2_(v0.y, ev0h), sf0h), pex0);
        u64t m1l = mul2_(mul2_(add2_(v1.x, ev1l), sf1l), pex1);
        u64t m1h = mul2_(mul2_(add2_(v1.y, ev1h), sf1h), pex1);
        float4 m0, m1;
        up2(m0.x, m0.y, m0l); up2(m0.z, m0.w, m0h);
        up2(m1.x, m1.y, m1l); up2(m1.z, m1.w, m1h);
        atomicAdd((float4*)(g_aggr + (size_t)d0 * 128 + 4 * lane), m0);
        atomicAdd((float4*)(g_aggr + (size_t)d1 * 128 + 4 * lane), m1);
    }
}

// ---------------- K3: normalize + add skip ----------------
__global__ __launch_bounds__(256)
void finalize_kernel(float* __restrict__ out)
{
    int t = blockIdx.x * blockDim.x + threadIdx.x;
    if (t >= NN * 32) return;
    int n = t >> 5;
    int g = t & 31;
    float d = g_denom[n * 4 + (g >> 3)];
    float inv = (d > 0.f) ? 1.0f / d : 0.f;
    float4 a = *(const float4*)(g_aggr + n * 128 + 4 * g);
    float4 o = *(const float4*)(out + n * 128 + 4 * g);
    o.x = fmaf(a.x, inv, o.x);
    o.y = fmaf(a.y, inv, o.y);
    o.z = fmaf(a.z, inv, o.z);
    o.w = fmaf(a.w, inv, o.w);
    *(float4*)(out + n * 128 + 4 * g) = o;
}

// ---------------- host ----------------
extern "C" void kernel_launch(void* const* d_in, const int* in_sizes, int n_in,
                              void* d_out, int out_size)
{
    const float* x         = (const float*)d_in[0];
    const float* edge_attr = (const float*)d_in[1];
    const float* rbf       = (const float*)d_in[2];
    const float* sbf       = (const float*)d_in[3];
    const float* w_rbf0    = (const float*)d_in[4];
    const float* w_rbf1    = (const float*)d_in[5];
    const float* w_sbf0    = (const float*)d_in[6];
    const float* w_sbf1    = (const float*)d_in[7];
    const float* w_ek      = (const float*)d_in[8];
    const float* w_ev      = (const float*)d_in[9];
    const float* w_k       = (const float*)d_in[10];
    const float* b_k       = (const float*)d_in[11];
    const float* w_q       = (const float*)d_in[12];
    const float* b_q       = (const float*)d_in[13];
    const float* w_v       = (const float*)d_in[14];
    const float* b_v       = (const float*)d_in[15];
    const float* w_skip    = (const float*)d_in[16];
    const float* b_skip    = (const float*)d_in[17];
    const int*   ei        = (const int*)d_in[18];
    float* out = (float*)d_out;

    void* p_aggr = nullptr; void* p_denom = nullptr;
    cudaGetSymbolAddress(&p_aggr, g_aggr);
    cudaGetSymbolAddress(&p_denom, g_denom);
    cudaMemsetAsync(p_aggr, 0, (size_t)NN * 128 * sizeof(float));
    cudaMemsetAsync(p_denom, 0, (size_t)NN * 4 * sizeof(float));

    combine_weights_kernel<<<6, 256>>>(w_rbf0, w_rbf1, w_sbf0, w_sbf1);

    int smem = 20288 * (int)sizeof(float);  // 81152 B -> 2 CTA/SM
    cudaFuncSetAttribute(node_kernel, cudaFuncAttributeMaxDynamicSharedMemorySize, smem);
    node_kernel<<<296, 256, smem>>>(x, rbf, w_ek, w_k, b_k, w_q, b_q,
                                    w_v, b_v, w_skip, b_skip, out);

    edge_kernel<<<296, 256>>>(edge_attr, sbf, w_ev, ei);

    finalize_kernel<<<(NN * 32 + 255) / 256, 256>>>(out);
}